// round 10
// baseline (speedup 1.0000x reference)
#include <cuda_runtime.h>
#include <stdint.h>

// ============================================================================
// SpecAugment, bit-exact vs JAX threefry2x32 (partitionable mode).
// R10: R8 + write-through stores. __stcs still allocates L2 lines for the
// 82 MB output stream, evicting parts of the 82 MB mel working set between
// graph replays. __stwt (st.global.wt) keeps stores out of L2 entirely ->
// whole L2 stays dedicated to mel, warm-replay reads come from LTS.
// Everything else identical to the verified R8 kernel (rel_err 0.0).
// ============================================================================

#define BATCH 64
#define NMELS 80
#define TLEN 4000
#define NQ (TLEN / 4)          // 1000 float4 groups per row
#define CHUNKS 16
#define ROWS_PER_BLK (NMELS / CHUNKS)   // 5

// ---------------- threefry2x32, constexpr-capable ----------------
struct U2 { uint32_t a, b; };

__host__ __device__ constexpr uint32_t rotl32c(uint32_t x, int d) {
    return (x << d) | (x >> (32 - d));
}

__host__ __device__ constexpr U2 tf2x32(uint32_t k0, uint32_t k1,
                                        uint32_t c0, uint32_t c1) {
    const uint32_t ks0 = k0, ks1 = k1, ks2 = 0x1BD11BDAu ^ k0 ^ k1;
    uint32_t x0 = c0 + ks0, x1 = c1 + ks1;
#define TF_RND(r) { x0 += x1; x1 = rotl32c(x1, r); x1 ^= x0; }
    TF_RND(13) TF_RND(15) TF_RND(26) TF_RND(6)
    x0 += ks1; x1 += ks2 + 1u;
    TF_RND(17) TF_RND(29) TF_RND(16) TF_RND(24)
    x0 += ks2; x1 += ks0 + 2u;
    TF_RND(13) TF_RND(15) TF_RND(26) TF_RND(6)
    x0 += ks0; x1 += ks1 + 3u;
    TF_RND(17) TF_RND(29) TF_RND(16) TF_RND(24)
    x0 += ks1; x1 += ks2 + 4u;
    TF_RND(13) TF_RND(15) TF_RND(26) TF_RND(6)
    x0 += ks2; x1 += ks0 + 5u;
#undef TF_RND
    return U2{x0, x1};
}

// Compile-time key folds: split(key(42), 4) and randint's internal split.
constexpr U2 KFW = tf2x32(0u, 42u, 0u, 0u);            // kf_w
constexpr U2 KFS = tf2x32(0u, 42u, 0u, 1u);            // kf_s
constexpr U2 KTW = tf2x32(0u, 42u, 0u, 2u);            // kt_w
constexpr U2 KTS = tf2x32(0u, 42u, 0u, 3u);            // kt_s
constexpr U2 KLO = tf2x32(KFW.a, KFW.b, 0u, 1u);       // randint lower-bits key

__device__ __forceinline__ uint32_t randbits32(uint32_t k0, uint32_t k1, uint32_t idx) {
    U2 r = tf2x32(k0, k1, 0u, idx);
    return r.a ^ r.b;
}

__device__ __forceinline__ float u32_to_unif(uint32_t bits) {
    return __uint_as_float((bits >> 9) | 0x3f800000u) - 1.0f;
}

// ---------------- fused kernel ----------------
__global__ void __launch_bounds__(256, 8)
fused_kernel(const float* __restrict__ mel,
             const int* __restrict__ lengths,
             float* __restrict__ out) {
    __shared__ int s_t0[5], s_tl[5], s_f0[2], s_fl[2];
    __shared__ uint32_t s_bits[NQ / 8];   // 4000 bits = 125 words

    const int b = blockIdx.x >> 4;        // batch
    const int chunk = blockIdx.x & 15;    // 5-row chunk within batch
    const int tid = threadIdx.x;

    // -- RNG draws (identical math to verified R1-R9) --
    if (tid < 5) {
        int j = tid;
        int valid = lengths[b];
        int mt = (int)((float)valid * 0.05f);
        int max_t = min(25, mt);
        max_t = min(max_t, valid - 1);
        max_t = max(0, max_t);
        uint32_t i = (uint32_t)(b * 5 + j);
        float ut = u32_to_unif(randbits32(KTW.a, KTW.b, i));
        int t = (int)floorf(ut * (float)(max_t + 1));
        if (valid <= 1) t = 0;
        float ut0 = u32_to_unif(randbits32(KTS.a, KTS.b, i));
        int t0 = (int)floorf(ut0 * (float)(valid - t + 1));
        s_t0[j] = t0;
        s_tl[j] = t;
    } else if (tid < 7) {
        int j = tid - 5;
        uint32_t i = (uint32_t)(b * 2 + j);
        int f = (int)(randbits32(KLO.a, KLO.b, i) & 15u);
        float uf = u32_to_unif(randbits32(KFS.a, KFS.b, i));
        int f0 = (int)floorf(uf * (float)(NMELS - f + 1));
        s_f0[j] = f0;
        s_fl[j] = f;
    }
    __syncthreads();

    // -- build 4000-bit time mask via interval spans --
    if (tid < NQ / 8) {
        const int base = tid * 32;
        uint32_t w = 0;
#pragma unroll
        for (int j = 0; j < 5; j++) {
            int lo = max(s_t0[j], base);
            int hi = min(s_t0[j] + s_tl[j], base + 32);
            if (hi > lo)
                w |= (uint32_t)(((1ull << (hi - lo)) - 1ull) << (lo - base));
        }
        s_bits[tid] = w;
    }
    __syncthreads();

    const int f00 = s_f0[0], fl0 = s_fl[0], f01 = s_f0[1], fl1 = s_fl[1];

    // -- stream 5 rows --
#pragma unroll
    for (int r = 0; r < ROWS_PER_BLK; r++) {
        const int m = chunk * ROWS_PER_BLK + r;
        const int row = b * NMELS + m;
        const float* mrow = mel + (size_t)row * TLEN;
        float* orow = out + (size_t)row * TLEN;
        const bool rz = ((unsigned)(m - f00) < (unsigned)fl0) |
                        ((unsigned)(m - f01) < (unsigned)fl1);

        if (rz) {
            const float4 z = make_float4(0.f, 0.f, 0.f, 0.f);
#pragma unroll
            for (int k = 0; k < 4; k++) {
                int idx = tid + k * 256;
                if (idx < NQ)
                    __stwt(reinterpret_cast<float4*>(orow + idx * 4), z);
            }
        } else {
            unsigned nib[4];
            float4 v[4];
#pragma unroll
            for (int k = 0; k < 4; k++) {
                int idx = tid + k * 256;
                nib[k] = (idx < NQ)
                    ? (s_bits[idx >> 3] >> ((idx & 7) * 4)) & 15u
                    : 0u;
            }
#pragma unroll
            for (int k = 0; k < 4; k++) {
                int idx = tid + k * 256;
                if (idx < NQ)
                    v[k] = *reinterpret_cast<const float4*>(mrow + idx * 4);
            }
#pragma unroll
            for (int k = 0; k < 4; k++) {
                int idx = tid + k * 256;
                if (idx >= NQ) continue;
                v[k].x = (nib[k] & 1u) ? 0.f : v[k].x;
                v[k].y = (nib[k] & 2u) ? 0.f : v[k].y;
                v[k].z = (nib[k] & 4u) ? 0.f : v[k].z;
                v[k].w = (nib[k] & 8u) ? 0.f : v[k].w;
                __stwt(reinterpret_cast<float4*>(orow + idx * 4), v[k]);
            }
        }
    }
}

extern "C" void kernel_launch(void* const* d_in, const int* in_sizes, int n_in,
                              void* d_out, int out_size) {
    const float* mel = (const float*)d_in[0];
    const int* lengths = (const int*)d_in[1];
    float* out = (float*)d_out;

    fused_kernel<<<BATCH * CHUNKS, 256>>>(mel, lengths, out);
}

// round 12
// speedup vs baseline: 1.0725x; 1.0725x over previous
#include <cuda_runtime.h>
#include <stdint.h>

// ============================================================================
// SpecAugment, bit-exact vs JAX threefry2x32 (partitionable mode).
// R12: R11 retried with the correct PTX encoding. sm_100 ptxas rejects the
// direct .L2::evict_last modifier on v4.f32 loads (needs v8.b32/v4.b64);
// the supported form is createpolicy.fractional.L2::evict_last +
// ld.global.nc.L2::cache_hint. Otherwise identical to the verified R8
// kernel: default→evict_last-hinted loads, __stcs stores.
// ============================================================================

#define BATCH 64
#define NMELS 80
#define TLEN 4000
#define NQ (TLEN / 4)          // 1000 float4 groups per row
#define CHUNKS 16
#define ROWS_PER_BLK (NMELS / CHUNKS)   // 5

// ---------------- threefry2x32, constexpr-capable ----------------
struct U2 { uint32_t a, b; };

__host__ __device__ constexpr uint32_t rotl32c(uint32_t x, int d) {
    return (x << d) | (x >> (32 - d));
}

__host__ __device__ constexpr U2 tf2x32(uint32_t k0, uint32_t k1,
                                        uint32_t c0, uint32_t c1) {
    const uint32_t ks0 = k0, ks1 = k1, ks2 = 0x1BD11BDAu ^ k0 ^ k1;
    uint32_t x0 = c0 + ks0, x1 = c1 + ks1;
#define TF_RND(r) { x0 += x1; x1 = rotl32c(x1, r); x1 ^= x0; }
    TF_RND(13) TF_RND(15) TF_RND(26) TF_RND(6)
    x0 += ks1; x1 += ks2 + 1u;
    TF_RND(17) TF_RND(29) TF_RND(16) TF_RND(24)
    x0 += ks2; x1 += ks0 + 2u;
    TF_RND(13) TF_RND(15) TF_RND(26) TF_RND(6)
    x0 += ks0; x1 += ks1 + 3u;
    TF_RND(17) TF_RND(29) TF_RND(16) TF_RND(24)
    x0 += ks1; x1 += ks2 + 4u;
    TF_RND(13) TF_RND(15) TF_RND(26) TF_RND(6)
    x0 += ks2; x1 += ks0 + 5u;
#undef TF_RND
    return U2{x0, x1};
}

// Compile-time key folds: split(key(42), 4) and randint's internal split.
constexpr U2 KFW = tf2x32(0u, 42u, 0u, 0u);            // kf_w
constexpr U2 KFS = tf2x32(0u, 42u, 0u, 1u);            // kf_s
constexpr U2 KTW = tf2x32(0u, 42u, 0u, 2u);            // kt_w
constexpr U2 KTS = tf2x32(0u, 42u, 0u, 3u);            // kt_s
constexpr U2 KLO = tf2x32(KFW.a, KFW.b, 0u, 1u);       // randint lower-bits key

__device__ __forceinline__ uint32_t randbits32(uint32_t k0, uint32_t k1, uint32_t idx) {
    U2 r = tf2x32(k0, k1, 0u, idx);
    return r.a ^ r.b;
}

__device__ __forceinline__ float u32_to_unif(uint32_t bits) {
    return __uint_as_float((bits >> 9) | 0x3f800000u) - 1.0f;
}

// L2 evict_last policy descriptor (uniform; CSE'd to one createpolicy)
__device__ __forceinline__ uint64_t evict_last_policy() {
    uint64_t pol;
    asm("createpolicy.fractional.L2::evict_last.b64 %0, 1.0;" : "=l"(pol));
    return pol;
}

// mel load: read-only, L2 high-retention via cache_hint
__device__ __forceinline__ float4 ldg_evict_last(const float4* p, uint64_t pol) {
    float4 v;
    asm volatile("ld.global.nc.L2::cache_hint.v4.f32 {%0, %1, %2, %3}, [%4], %5;"
                 : "=f"(v.x), "=f"(v.y), "=f"(v.z), "=f"(v.w)
                 : "l"(p), "l"(pol));
    return v;
}

// ---------------- fused kernel ----------------
__global__ void __launch_bounds__(256, 8)
fused_kernel(const float* __restrict__ mel,
             const int* __restrict__ lengths,
             float* __restrict__ out) {
    __shared__ int s_t0[5], s_tl[5], s_f0[2], s_fl[2];
    __shared__ uint32_t s_bits[NQ / 8];   // 4000 bits = 125 words

    const int b = blockIdx.x >> 4;        // batch
    const int chunk = blockIdx.x & 15;    // 5-row chunk within batch
    const int tid = threadIdx.x;

    // -- RNG draws (identical math to verified R1-R10) --
    if (tid < 5) {
        int j = tid;
        int valid = lengths[b];
        int mt = (int)((float)valid * 0.05f);
        int max_t = min(25, mt);
        max_t = min(max_t, valid - 1);
        max_t = max(0, max_t);
        uint32_t i = (uint32_t)(b * 5 + j);
        float ut = u32_to_unif(randbits32(KTW.a, KTW.b, i));
        int t = (int)floorf(ut * (float)(max_t + 1));
        if (valid <= 1) t = 0;
        float ut0 = u32_to_unif(randbits32(KTS.a, KTS.b, i));
        int t0 = (int)floorf(ut0 * (float)(valid - t + 1));
        s_t0[j] = t0;
        s_tl[j] = t;
    } else if (tid < 7) {
        int j = tid - 5;
        uint32_t i = (uint32_t)(b * 2 + j);
        int f = (int)(randbits32(KLO.a, KLO.b, i) & 15u);
        float uf = u32_to_unif(randbits32(KFS.a, KFS.b, i));
        int f0 = (int)floorf(uf * (float)(NMELS - f + 1));
        s_f0[j] = f0;
        s_fl[j] = f;
    }
    __syncthreads();

    // -- build 4000-bit time mask via interval spans --
    if (tid < NQ / 8) {
        const int base = tid * 32;
        uint32_t w = 0;
#pragma unroll
        for (int j = 0; j < 5; j++) {
            int lo = max(s_t0[j], base);
            int hi = min(s_t0[j] + s_tl[j], base + 32);
            if (hi > lo)
                w |= (uint32_t)(((1ull << (hi - lo)) - 1ull) << (lo - base));
        }
        s_bits[tid] = w;
    }
    __syncthreads();

    const int f00 = s_f0[0], fl0 = s_fl[0], f01 = s_f0[1], fl1 = s_fl[1];
    const uint64_t pol = evict_last_policy();

    // -- stream 5 rows --
#pragma unroll
    for (int r = 0; r < ROWS_PER_BLK; r++) {
        const int m = chunk * ROWS_PER_BLK + r;
        const int row = b * NMELS + m;
        const float* mrow = mel + (size_t)row * TLEN;
        float* orow = out + (size_t)row * TLEN;
        const bool rz = ((unsigned)(m - f00) < (unsigned)fl0) |
                        ((unsigned)(m - f01) < (unsigned)fl1);

        if (rz) {
            const float4 z = make_float4(0.f, 0.f, 0.f, 0.f);
#pragma unroll
            for (int k = 0; k < 4; k++) {
                int idx = tid + k * 256;
                if (idx < NQ)
                    __stcs(reinterpret_cast<float4*>(orow + idx * 4), z);
            }
        } else {
            unsigned nib[4];
            float4 v[4];
#pragma unroll
            for (int k = 0; k < 4; k++) {
                int idx = tid + k * 256;
                nib[k] = (idx < NQ)
                    ? (s_bits[idx >> 3] >> ((idx & 7) * 4)) & 15u
                    : 0u;
            }
#pragma unroll
            for (int k = 0; k < 4; k++) {
                int idx = tid + k * 256;
                if (idx < NQ)
                    v[k] = ldg_evict_last(reinterpret_cast<const float4*>(mrow + idx * 4), pol);
            }
#pragma unroll
            for (int k = 0; k < 4; k++) {
                int idx = tid + k * 256;
                if (idx >= NQ) continue;
                v[k].x = (nib[k] & 1u) ? 0.f : v[k].x;
                v[k].y = (nib[k] & 2u) ? 0.f : v[k].y;
                v[k].z = (nib[k] & 4u) ? 0.f : v[k].z;
                v[k].w = (nib[k] & 8u) ? 0.f : v[k].w;
                __stcs(reinterpret_cast<float4*>(orow + idx * 4), v[k]);
            }
        }
    }
}

extern "C" void kernel_launch(void* const* d_in, const int* in_sizes, int n_in,
                              void* d_out, int out_size) {
    const float* mel = (const float*)d_in[0];
    const int* lengths = (const int*)d_in[1];
    float* out = (float*)d_out;

    fused_kernel<<<BATCH * CHUNKS, 256>>>(mel, lengths, out);
}